// round 8
// baseline (speedup 1.0000x reference)
#include <cuda_runtime.h>
#include <cuda_fp16.h>
#include <cstdint>
#include <math.h>

// Problem constants
#define D_MODEL 1024
#define NHEADS  16
#define DK      64
#define BATCH   2048
#define SEQ     20
#define M_TOTAL (BATCH * SEQ)   // 40960

// ---------------------------------------------------------------------------
// Scratch (fp16)
// ---------------------------------------------------------------------------
__device__ __half g_xh[(size_t)M_TOTAL * D_MODEL];
__device__ __half g_wh[3][(size_t)D_MODEL * D_MODEL];
__device__ __half g_qh[(size_t)M_TOTAL * D_MODEL];
__device__ __half g_kh[(size_t)M_TOTAL * D_MODEL];
__device__ __half g_vh[(size_t)M_TOTAL * D_MODEL];

// ---------------------------------------------------------------------------
// Merged fp32 -> fp16 conversion with streaming 16B loads/stores.
// ---------------------------------------------------------------------------
struct alignas(16) Half8 { __half2 a, b, c, d; };

#define XBLKS 10240
#define WBLKS 256

__global__ __launch_bounds__(256) void f2h_multi(
    const float* __restrict__ X,
    const float* __restrict__ Wq, const float* __restrict__ Wk, const float* __restrict__ Wv)
{
    const float* src;
    __half* dst;
    int local;
    if (blockIdx.x < XBLKS) {
        src = X; dst = g_xh; local = blockIdx.x;
    } else {
        int w = (blockIdx.x - XBLKS) / WBLKS;
        local = (blockIdx.x - XBLKS) % WBLKS;
        src = (w == 0) ? Wq : (w == 1) ? Wk : Wv;
        dst = &g_wh[w][0];
    }
    int c0 = (local * 256 + threadIdx.x) * 2;    // exact fit
    float4 v[4];
    #pragma unroll
    for (int u = 0; u < 4; u++)
        v[u] = __ldcs(&((const float4*)src)[c0 * 2 + u]);
    #pragma unroll
    for (int u = 0; u < 2; u++) {
        Half8 h;
        h.a = __floats2half2_rn(v[2 * u].x,     v[2 * u].y);
        h.b = __floats2half2_rn(v[2 * u].z,     v[2 * u].w);
        h.c = __floats2half2_rn(v[2 * u + 1].x, v[2 * u + 1].y);
        h.d = __floats2half2_rn(v[2 * u + 1].z, v[2 * u + 1].w);
        __stcs((float4*)&((Half8*)dst)[c0 + u], *(float4*)&h);
    }
}

// ---------------------------------------------------------------------------
// fp16 m16n8k16 MMA, fp32 accumulate
// ---------------------------------------------------------------------------
__device__ __forceinline__ void mma16(float* c, const uint32_t* a, const uint32_t* b) {
    asm volatile(
        "mma.sync.aligned.m16n8k16.row.col.f32.f16.f16.f32 "
        "{%0,%1,%2,%3}, {%4,%5,%6,%7}, {%8,%9}, {%0,%1,%2,%3};"
        : "+f"(c[0]), "+f"(c[1]), "+f"(c[2]), "+f"(c[3])
        : "r"(a[0]), "r"(a[1]), "r"(a[2]), "r"(a[3]),
          "r"(b[0]), "r"(b[1]));
}

__device__ __forceinline__ void cp16(uint32_t saddr, const void* g) {
    asm volatile("cp.async.cg.shared.global [%0], [%1], 16;\n" :: "r"(saddr), "l"(g));
}
#define CP_COMMIT() asm volatile("cp.async.commit_group;\n" ::: "memory")
#define CP_WAIT(n)  asm volatile("cp.async.wait_group %0;\n" :: "n"(n) : "memory")

__device__ __forceinline__ uint32_t smem_u32(const void* p) {
    uint32_t a;
    asm("{ .reg .u64 t; cvta.to.shared.u64 t, %1; cvt.u32.u64 %0, t; }"
        : "=r"(a) : "l"(p));
    return a;
}

// ---------------------------------------------------------------------------
// Projection GEMM: Y = X @ W^T + b, fp16 output. 2 CTAs/SM.
// BM=128, BN=128, BK=32, 4-stage cp.async, ONE __syncthreads per ktile.
// (Safe: stage written at iter kt is (kt+3)%4 = (kt-1)%4, last read during
//  iter kt-1, which completed before this iter's barrier.)
// 8 warps (2x4), warp tile 64x32.
// Smem rows 20-word stride: (g*20 + tq + {0,4}) mod 32 covers all banks.
// ---------------------------------------------------------------------------
#define GM_BM 128
#define GM_BN 128
#define GM_BK 32
#define WSTRIDE 20
#define A_STG_WORDS (GM_BM * WSTRIDE)     // 2560
#define B_STG_WORDS (GM_BN * WSTRIDE)     // 2560
#define STG_WORDS   (A_STG_WORDS + B_STG_WORDS)  // 5120
#define NSTAGE 4
#define GM_SMEM_BYTES (NSTAGE * STG_WORDS * 4)   // 81920
#define GM_KT (D_MODEL / GM_BK)           // 32

__global__ __launch_bounds__(256, 2) void proj_gemm(
    const float* __restrict__ bq, const float* __restrict__ bk, const float* __restrict__ bv)
{
    extern __shared__ uint32_t smem[];
    const uint32_t sb = smem_u32(smem);

    const int tid  = threadIdx.x;
    const int lane = tid & 31;
    const int warp = tid >> 5;
    const int wr   = warp >> 2;     // 0..1
    const int wc   = warp & 3;      // 0..3
    const int g    = lane >> 2;
    const int tq   = lane & 3;

    const int proj  = blockIdx.x >> 3;              // 0..2
    const int nBase = (blockIdx.x & 7) * GM_BN;     // 0..896
    const int mBase = blockIdx.y * GM_BM;

    const __half* Wp = g_wh[proj];

    auto load_stage = [&](int stg, int kt) {
        uint32_t base = sb + stg * (STG_WORDS * 4);
        int k0 = kt * GM_BK;
        #pragma unroll
        for (int i = 0; i < 2; i++) {
            int ch = tid + i * 256;       // 0..511
            int r = ch >> 2, c = ch & 3;
            cp16(base + (r * WSTRIDE + c * 4) * 4,
                 &g_xh[(size_t)(mBase + r) * D_MODEL + k0 + c * 8]);
        }
        #pragma unroll
        for (int i = 0; i < 2; i++) {
            int ch = tid + i * 256;
            int r = ch >> 2, c = ch & 3;
            cp16(base + (A_STG_WORDS + r * WSTRIDE + c * 4) * 4,
                 &Wp[(size_t)(nBase + r) * D_MODEL + k0 + c * 8]);
        }
        CP_COMMIT();
    };

    float c[4][4][4];
    #pragma unroll
    for (int mt = 0; mt < 4; mt++)
        #pragma unroll
        for (int nt = 0; nt < 4; nt++)
            #pragma unroll
            for (int i = 0; i < 4; i++) c[mt][nt][i] = 0.f;

    load_stage(0, 0);
    load_stage(1, 1);
    load_stage(2, 2);

    for (int kt = 0; kt < GM_KT; kt++) {
        int stg = kt & (NSTAGE - 1);
        CP_WAIT(2);           // stage kt complete (<=2 groups still in flight)
        __syncthreads();      // single barrier: readiness + overwrite safety
        if (kt + 3 < GM_KT) load_stage((kt + 3) & (NSTAGE - 1), kt + 3);

        const uint32_t* sAw = smem + stg * STG_WORDS;
        const uint32_t* sBw = sAw + A_STG_WORDS;

        #pragma unroll
        for (int ks = 0; ks < 2; ks++) {
            const int kw = ks * 8 + tq;
            uint32_t af[4][4], bf[4][2];
            #pragma unroll
            for (int mt = 0; mt < 4; mt++) {
                int rb = (wr * 64 + mt * 16 + g) * WSTRIDE + kw;
                af[mt][0] = sAw[rb];
                af[mt][1] = sAw[rb + 8 * WSTRIDE];
                af[mt][2] = sAw[rb + 4];
                af[mt][3] = sAw[rb + 8 * WSTRIDE + 4];
            }
            #pragma unroll
            for (int nt = 0; nt < 4; nt++) {
                int rb = (wc * 32 + nt * 8 + g) * WSTRIDE + kw;
                bf[nt][0] = sBw[rb];
                bf[nt][1] = sBw[rb + 4];
            }
            #pragma unroll
            for (int mt = 0; mt < 4; mt++)
                #pragma unroll
                for (int nt = 0; nt < 4; nt++)
                    mma16(c[mt][nt], af[mt], bf[nt]);
        }
    }

    // Epilogue: bias add + store fp16
    const float* bp = (proj == 0) ? bq : (proj == 1) ? bk : bv;
    __half* outp    = (proj == 0) ? g_qh : (proj == 1) ? g_kh : g_vh;
    #pragma unroll
    for (int mt = 0; mt < 4; mt++) {
        #pragma unroll
        for (int nt = 0; nt < 4; nt++) {
            int row = mBase + wr * 64 + mt * 16 + g;
            int col = nBase + wc * 32 + nt * 8 + 2 * tq;
            float b0 = bp[col], b1 = bp[col + 1];
            __half2 h01 = __floats2half2_rn(c[mt][nt][0] + b0, c[mt][nt][1] + b1);
            __half2 h23 = __floats2half2_rn(c[mt][nt][2] + b0, c[mt][nt][3] + b1);
            *(__half2*)&outp[(size_t)row * D_MODEL + col] = h01;
            *(__half2*)&outp[(size_t)(row + 8) * D_MODEL + col] = h23;
        }
    }
}

// ---------------------------------------------------------------------------
// Attention + decay. fp16 gmem -> fp32 smem (cvt once at load).
// wgtT[j][i] = ssc[i][j]*sinv[i] - |i-j| precomputed. Block per (b,h).
// ---------------------------------------------------------------------------
struct alignas(8) Half4 { __half2 a, b; };

__global__ __launch_bounds__(128) void attn_kernel(
    const int* __restrict__ lenbuf, float* __restrict__ out)
{
    const int bh = blockIdx.x;
    const int b  = bh >> 4;
    const int h  = bh & 15;
    const int tid = threadIdx.x;

    __shared__ __align__(16) float sq[SEQ][68];
    __shared__ __align__(16) float sk[SEQ][68];
    __shared__ __align__(16) float sv[SEQ][68];
    __shared__ float ssc[SEQ][24];
    __shared__ float sinv[SEQ];
    __shared__ __align__(16) float wgtT[SEQ][24];   // [j][i]

    {
        size_t base = (size_t)(b * SEQ) * D_MODEL + h * DK;
        for (int e = tid; e < SEQ * (DK / 8); e += 128) {
            int s = e >> 3, d8 = (e & 7) * 8;
            size_t gi = base + (size_t)s * D_MODEL + d8;
            Half4 q0 = *(const Half4*)&g_qh[gi];
            Half4 q1 = *(const Half4*)&g_qh[gi + 4];
            Half4 k0 = *(const Half4*)&g_kh[gi];
            Half4 k1 = *(const Half4*)&g_kh[gi + 4];
            Half4 v0 = *(const Half4*)&g_vh[gi];
            Half4 v1 = *(const Half4*)&g_vh[gi + 4];
            float2 f;
            f = __half22float2(q0.a); sq[s][d8 + 0] = f.x; sq[s][d8 + 1] = f.y;
            f = __half22float2(q0.b); sq[s][d8 + 2] = f.x; sq[s][d8 + 3] = f.y;
            f = __half22float2(q1.a); sq[s][d8 + 4] = f.x; sq[s][d8 + 5] = f.y;
            f = __half22float2(q1.b); sq[s][d8 + 6] = f.x; sq[s][d8 + 7] = f.y;
            f = __half22float2(k0.a); sk[s][d8 + 0] = f.x; sk[s][d8 + 1] = f.y;
            f = __half22float2(k0.b); sk[s][d8 + 2] = f.x; sk[s][d8 + 3] = f.y;
            f = __half22float2(k1.a); sk[s][d8 + 4] = f.x; sk[s][d8 + 5] = f.y;
            f = __half22float2(k1.b); sk[s][d8 + 6] = f.x; sk[s][d8 + 7] = f.y;
            f = __half22float2(v0.a); sv[s][d8 + 0] = f.x; sv[s][d8 + 1] = f.y;
            f = __half22float2(v0.b); sv[s][d8 + 2] = f.x; sv[s][d8 + 3] = f.y;
            f = __half22float2(v1.a); sv[s][d8 + 4] = f.x; sv[s][d8 + 5] = f.y;
            f = __half22float2(v1.b); sv[s][d8 + 6] = f.x; sv[s][d8 + 7] = f.y;
        }
    }
    __syncthreads();

    // length may be int64 or int32 (jax x64 config). All lengths >= 1,
    // so int32-view word 1 == 0 iff buffer is int64.
    bool is64 = (lenbuf[1] == 0);
    int len = is64 ? lenbuf[2 * b] : lenbuf[b];

    // Scores: 2x2 register tiles on threads 0..99, float4 loads
    if (tid < 100) {
        int i0 = (tid / 10) * 2, j0 = (tid % 10) * 2;
        float a00 = 0.f, a01 = 0.f, a10 = 0.f, a11 = 0.f;
        #pragma unroll
        for (int d4 = 0; d4 < DK / 4; d4++) {
            float4 q0 = *(const float4*)&sq[i0][4 * d4];
            float4 q1 = *(const float4*)&sq[i0 + 1][4 * d4];
            float4 k0 = *(const float4*)&sk[j0][4 * d4];
            float4 k1 = *(const float4*)&sk[j0 + 1][4 * d4];
            a00 += q0.x * k0.x + q0.y * k0.y + q0.z * k0.z + q0.w * k0.w;
            a01 += q0.x * k1.x + q0.y * k1.y + q0.z * k1.z + q0.w * k1.w;
            a10 += q1.x * k0.x + q1.y * k0.y + q1.z * k0.z + q1.w * k0.w;
            a11 += q1.x * k1.x + q1.y * k1.y + q1.z * k1.z + q1.w * k1.w;
        }
        bool m0 = (j0 < len), m1 = (j0 + 1 < len);
        ssc[i0][j0]         = m0 ? __expf(a00 * 0.125f) : 0.f;
        ssc[i0][j0 + 1]     = m1 ? __expf(a01 * 0.125f) : 0.f;
        ssc[i0 + 1][j0]     = m0 ? __expf(a10 * 0.125f) : 0.f;
        ssc[i0 + 1][j0 + 1] = m1 ? __expf(a11 * 0.125f) : 0.f;
    }
    __syncthreads();

    if (tid < SEQ) {
        float s = 0.f;
        #pragma unroll
        for (int j = 0; j < SEQ; j++) s += ssc[tid][j];
        sinv[tid] = 1.f / (s + 1e-8f);
    }
    __syncthreads();

    for (int e = tid; e < SEQ * SEQ; e += 128) {
        int i = e % SEQ, j = e / SEQ;
        wgtT[j][i] = ssc[i][j] * sinv[i] - (float)((i > j) ? (i - j) : (j - i));
    }
    __syncthreads();

    // Output: 4 rows x 4 cols per thread on threads 0..79
    if (tid < 80) {
        int i0 = (tid / 16) * 4;
        int d0 = (tid & 15) * 4;
        float4 o0 = {0, 0, 0, 0}, o1 = {0, 0, 0, 0}, o2 = {0, 0, 0, 0}, o3 = {0, 0, 0, 0};
        #pragma unroll
        for (int j = 0; j < SEQ; j++) {
            float4 vv = *(const float4*)&sv[j][d0];
            float4 w  = *(const float4*)&wgtT[j][i0];
            o0.x += w.x * vv.x; o0.y += w.x * vv.y; o0.z += w.x * vv.z; o0.w += w.x * vv.w;
            o1.x += w.y * vv.x; o1.y += w.y * vv.y; o1.z += w.y * vv.z; o1.w += w.y * vv.w;
            o2.x += w.z * vv.x; o2.y += w.z * vv.y; o2.z += w.z * vv.z; o2.w += w.z * vv.w;
            o3.x += w.w * vv.x; o3.y += w.w * vv.y; o3.z += w.w * vv.z; o3.w += w.w * vv.w;
        }
        size_t base = (size_t)(b * SEQ + i0) * D_MODEL + h * DK + d0;
        *(float4*)&out[base]               = o0;
        *(float4*)&out[base + D_MODEL]     = o1;
        *(float4*)&out[base + 2 * D_MODEL] = o2;
        *(float4*)&out[base + 3 * D_MODEL] = o3;
    }
}

// ---------------------------------------------------------------------------
// Inputs (metadata order): Q, W_Q, b_Q, W_K, b_K, W_V, b_V, length
// ---------------------------------------------------------------------------
extern "C" void kernel_launch(void* const* d_in, const int* in_sizes, int n_in,
                              void* d_out, int out_size)
{
    const float* X  = (const float*)d_in[0];
    const float* Wq = (const float*)d_in[1];
    const float* bq = (const float*)d_in[2];
    const float* Wk = (const float*)d_in[3];
    const float* bk = (const float*)d_in[4];
    const float* Wv = (const float*)d_in[5];
    const float* bv = (const float*)d_in[6];
    const int*   ln = (const int*)d_in[7];

    f2h_multi<<<XBLKS + 3 * WBLKS, 256>>>(X, Wq, Wk, Wv);

    cudaFuncSetAttribute(proj_gemm,
                         cudaFuncAttributeMaxDynamicSharedMemorySize, GM_SMEM_BYTES);

    // grid.x fastest = (proj, n-tile): X m-tile reused 24x from L2, W resident
    dim3 grid(3 * (D_MODEL / GM_BN), M_TOTAL / GM_BM);   // (24, 320)
    proj_gemm<<<grid, 256, GM_SMEM_BYTES>>>(bq, bk, bv);

    attn_kernel<<<BATCH * NHEADS, 128>>>(ln, (float*)d_out);
}

// round 9
// speedup vs baseline: 1.1011x; 1.1011x over previous
#include <cuda_runtime.h>
#include <cuda_fp16.h>
#include <cstdint>
#include <math.h>

// Problem constants
#define D_MODEL 1024
#define NHEADS  16
#define DK      64
#define BATCH   2048
#define SEQ     20
#define M_TOTAL (BATCH * SEQ)   // 40960

// ---------------------------------------------------------------------------
// Scratch (fp16)
// ---------------------------------------------------------------------------
__device__ __half g_xh[(size_t)M_TOTAL * D_MODEL];
__device__ __half g_wh[3][(size_t)D_MODEL * D_MODEL];
__device__ __half g_qh[(size_t)M_TOTAL * D_MODEL];
__device__ __half g_kh[(size_t)M_TOTAL * D_MODEL];
__device__ __half g_vh[(size_t)M_TOTAL * D_MODEL];

// ---------------------------------------------------------------------------
// Merged fp32 -> fp16 conversion with streaming 16B loads/stores.
// ---------------------------------------------------------------------------
struct alignas(16) Half8 { __half2 a, b, c, d; };
struct alignas(8)  Half4 { __half2 a, b; };

#define XBLKS 10240
#define WBLKS 256

__global__ __launch_bounds__(256) void f2h_multi(
    const float* __restrict__ X,
    const float* __restrict__ Wq, const float* __restrict__ Wk, const float* __restrict__ Wv)
{
    const float* src;
    __half* dst;
    int local;
    if (blockIdx.x < XBLKS) {
        src = X; dst = g_xh; local = blockIdx.x;
    } else {
        int w = (blockIdx.x - XBLKS) / WBLKS;
        local = (blockIdx.x - XBLKS) % WBLKS;
        src = (w == 0) ? Wq : (w == 1) ? Wk : Wv;
        dst = &g_wh[w][0];
    }
    int c0 = (local * 256 + threadIdx.x) * 2;    // exact fit
    float4 v[4];
    #pragma unroll
    for (int u = 0; u < 4; u++)
        v[u] = __ldcs(&((const float4*)src)[c0 * 2 + u]);
    #pragma unroll
    for (int u = 0; u < 2; u++) {
        Half8 h;
        h.a = __floats2half2_rn(v[2 * u].x,     v[2 * u].y);
        h.b = __floats2half2_rn(v[2 * u].z,     v[2 * u].w);
        h.c = __floats2half2_rn(v[2 * u + 1].x, v[2 * u + 1].y);
        h.d = __floats2half2_rn(v[2 * u + 1].z, v[2 * u + 1].w);
        __stcs((float4*)&((Half8*)dst)[c0 + u], *(float4*)&h);
    }
}

// ---------------------------------------------------------------------------
// MMA helpers
// ---------------------------------------------------------------------------
__device__ __forceinline__ void mma16(float* c, const uint32_t* a, const uint32_t* b) {
    asm volatile(
        "mma.sync.aligned.m16n8k16.row.col.f32.f16.f16.f32 "
        "{%0,%1,%2,%3}, {%4,%5,%6,%7}, {%8,%9}, {%0,%1,%2,%3};"
        : "+f"(c[0]), "+f"(c[1]), "+f"(c[2]), "+f"(c[3])
        : "r"(a[0]), "r"(a[1]), "r"(a[2]), "r"(a[3]),
          "r"(b[0]), "r"(b[1]));
}

__device__ __forceinline__ void ldmatrix_x4(uint32_t* r, uint32_t addr) {
    asm volatile("ldmatrix.sync.aligned.m8n8.x4.shared.b16 {%0,%1,%2,%3}, [%4];"
                 : "=r"(r[0]), "=r"(r[1]), "=r"(r[2]), "=r"(r[3]) : "r"(addr));
}
__device__ __forceinline__ void ldmatrix_x2(uint32_t* r, uint32_t addr) {
    asm volatile("ldmatrix.sync.aligned.m8n8.x2.shared.b16 {%0,%1}, [%2];"
                 : "=r"(r[0]), "=r"(r[1]) : "r"(addr));
}

__device__ __forceinline__ void cp16(uint32_t saddr, const void* g) {
    asm volatile("cp.async.cg.shared.global [%0], [%1], 16;\n" :: "r"(saddr), "l"(g));
}
#define CP_COMMIT() asm volatile("cp.async.commit_group;\n" ::: "memory")
#define CP_WAIT(n)  asm volatile("cp.async.wait_group %0;\n" :: "n"(n) : "memory")

__device__ __forceinline__ uint32_t smem_u32(const void* p) {
    uint32_t a;
    asm("{ .reg .u64 t; cvta.to.shared.u64 t, %1; cvt.u32.u64 %0, t; }"
        : "=r"(a) : "l"(p));
    return a;
}

// ---------------------------------------------------------------------------
// Projection GEMM (exact R7 config — best measured): Y = X @ W^T + b.
// BM=128, BN=128, BK=32, 3-stage cp.async, 2 CTAs/SM.
// ---------------------------------------------------------------------------
#define GM_BM 128
#define GM_BN 128
#define GM_BK 32
#define WSTRIDE 20
#define A_STG_WORDS (GM_BM * WSTRIDE)     // 2560
#define B_STG_WORDS (GM_BN * WSTRIDE)     // 2560
#define STG_WORDS   (A_STG_WORDS + B_STG_WORDS)  // 5120
#define NSTAGE 3
#define GM_SMEM_BYTES (NSTAGE * STG_WORDS * 4)   // 61440
#define GM_KT (D_MODEL / GM_BK)           // 32

__global__ __launch_bounds__(256, 2) void proj_gemm(
    const float* __restrict__ bq, const float* __restrict__ bk, const float* __restrict__ bv)
{
    extern __shared__ uint32_t smem[];
    const uint32_t sb = smem_u32(smem);

    const int tid  = threadIdx.x;
    const int lane = tid & 31;
    const int warp = tid >> 5;
    const int wr   = warp >> 2;
    const int wc   = warp & 3;
    const int g    = lane >> 2;
    const int tq   = lane & 3;

    const int proj  = blockIdx.x >> 3;
    const int nBase = (blockIdx.x & 7) * GM_BN;
    const int mBase = blockIdx.y * GM_BM;

    const __half* Wp = g_wh[proj];

    auto load_stage = [&](int stg, int kt) {
        uint32_t base = sb + stg * (STG_WORDS * 4);
        int k0 = kt * GM_BK;
        #pragma unroll
        for (int i = 0; i < 2; i++) {
            int ch = tid + i * 256;
            int r = ch >> 2, c = ch & 3;
            cp16(base + (r * WSTRIDE + c * 4) * 4,
                 &g_xh[(size_t)(mBase + r) * D_MODEL + k0 + c * 8]);
        }
        #pragma unroll
        for (int i = 0; i < 2; i++) {
            int ch = tid + i * 256;
            int r = ch >> 2, c = ch & 3;
            cp16(base + (A_STG_WORDS + r * WSTRIDE + c * 4) * 4,
                 &Wp[(size_t)(nBase + r) * D_MODEL + k0 + c * 8]);
        }
        CP_COMMIT();
    };

    float c[4][4][4];
    #pragma unroll
    for (int mt = 0; mt < 4; mt++)
        #pragma unroll
        for (int nt = 0; nt < 4; nt++)
            #pragma unroll
            for (int i = 0; i < 4; i++) c[mt][nt][i] = 0.f;

    load_stage(0, 0);
    load_stage(1, 1);

    for (int kt = 0; kt < GM_KT; kt++) {
        int stg = kt % NSTAGE;
        if (kt + 2 < GM_KT) load_stage((kt + 2) % NSTAGE, kt + 2);
        if (kt < GM_KT - 2)      CP_WAIT(2);
        else if (kt == GM_KT - 2) CP_WAIT(1);
        else                      CP_WAIT(0);
        __syncthreads();

        const uint32_t* sAw = smem + stg * STG_WORDS;
        const uint32_t* sBw = sAw + A_STG_WORDS;

        #pragma unroll
        for (int ks = 0; ks < 2; ks++) {
            const int kw = ks * 8 + tq;
            uint32_t af[4][4], bf[4][2];
            #pragma unroll
            for (int mt = 0; mt < 4; mt++) {
                int rb = (wr * 64 + mt * 16 + g) * WSTRIDE + kw;
                af[mt][0] = sAw[rb];
                af[mt][1] = sAw[rb + 8 * WSTRIDE];
                af[mt][2] = sAw[rb + 4];
                af[mt][3] = sAw[rb + 8 * WSTRIDE + 4];
            }
            #pragma unroll
            for (int nt = 0; nt < 4; nt++) {
                int rb = (wc * 32 + nt * 8 + g) * WSTRIDE + kw;
                bf[nt][0] = sBw[rb];
                bf[nt][1] = sBw[rb + 4];
            }
            #pragma unroll
            for (int mt = 0; mt < 4; mt++)
                #pragma unroll
                for (int nt = 0; nt < 4; nt++)
                    mma16(c[mt][nt], af[mt], bf[nt]);
        }
        __syncthreads();
    }

    const float* bp = (proj == 0) ? bq : (proj == 1) ? bk : bv;
    __half* outp    = (proj == 0) ? g_qh : (proj == 1) ? g_kh : g_vh;
    #pragma unroll
    for (int mt = 0; mt < 4; mt++) {
        #pragma unroll
        for (int nt = 0; nt < 4; nt++) {
            int row = mBase + wr * 64 + mt * 16 + g;
            int col = nBase + wc * 32 + nt * 8 + 2 * tq;
            float b0 = bp[col], b1 = bp[col + 1];
            __half2 h01 = __floats2half2_rn(c[mt][nt][0] + b0, c[mt][nt][1] + b1);
            __half2 h23 = __floats2half2_rn(c[mt][nt][2] + b0, c[mt][nt][3] + b1);
            *(__half2*)&outp[(size_t)row * D_MODEL + col] = h01;
            *(__half2*)&outp[(size_t)(row + 8) * D_MODEL + col] = h23;
        }
    }
}

// ---------------------------------------------------------------------------
// Attention + decay. Score phase on tensor cores (M pad 32, N pad 24).
// q/k kept fp16 in smem for ldmatrix; v fp32 for FFMA output phase.
// Block per (b,h), 128 threads = 4 warps (warps 0-2 do the score MMA).
// ---------------------------------------------------------------------------
#define QK_STRIDE 72   // halves per row (144 B: rows walk distinct bank-quads)

__global__ __launch_bounds__(128) void attn_kernel(
    const int* __restrict__ lenbuf, float* __restrict__ out)
{
    const int bh = blockIdx.x;
    const int b  = bh >> 4;
    const int h  = bh & 15;
    const int tid  = threadIdx.x;
    const int warp = tid >> 5;
    const int lane = tid & 31;

    __shared__ __align__(16) __half sqh[32][QK_STRIDE];
    __shared__ __align__(16) __half skh[24][QK_STRIDE];
    __shared__ __align__(16) float sv[SEQ][68];
    __shared__ float ssc[SEQ][24];
    __shared__ float sinv[SEQ];
    __shared__ __align__(16) float wgtT[SEQ][24];   // [j][i]

    // Zero-fill q/k smem (padded rows must be 0 so MMA garbage is benign)
    for (int i = tid; i < 32 * (QK_STRIDE / 2); i += 128) ((uint32_t*)sqh)[i] = 0;
    for (int i = tid; i < 24 * (QK_STRIDE / 2); i += 128) ((uint32_t*)skh)[i] = 0;
    __syncthreads();

    // Load q/k fp16 straight through; v converted to fp32
    {
        size_t base = (size_t)(b * SEQ) * D_MODEL + h * DK;
        for (int e = tid; e < SEQ * (DK / 8); e += 128) {
            int s = e >> 3, d8 = (e & 7) * 8;
            size_t gi = base + (size_t)s * D_MODEL + d8;
            Half8 q8 = *(const Half8*)&g_qh[gi];
            Half8 k8 = *(const Half8*)&g_kh[gi];
            Half8 v8 = *(const Half8*)&g_vh[gi];
            *(Half8*)&sqh[s][d8] = q8;
            *(Half8*)&skh[s][d8] = k8;
            float2 fa = __half22float2(v8.a), fb = __half22float2(v8.b);
            float2 fc = __half22float2(v8.c), fd = __half22float2(v8.d);
            float4 v0 = make_float4(fa.x, fa.y, fb.x, fb.y);
            float4 v1 = make_float4(fc.x, fc.y, fd.x, fd.y);
            *(float4*)&sv[s][d8]     = v0;
            *(float4*)&sv[s][d8 + 4] = v1;
        }
    }
    __syncthreads();

    // length may be int64 or int32 (jax x64 config). All lengths >= 1,
    // so int32-view word 1 == 0 iff buffer is int64.
    bool is64 = (lenbuf[1] == 0);
    int len = is64 ? lenbuf[2 * b] : lenbuf[b];

    // Score phase: warps 0-2, each computes cols [8w, 8w+8) for all 32 rows.
    if (warp < 3) {
        float c[2][4];
        #pragma unroll
        for (int mt = 0; mt < 2; mt++)
            #pragma unroll
            for (int i = 0; i < 4; i++) c[mt][i] = 0.f;

        const uint32_t sq_base = smem_u32(&sqh[0][0]);
        const uint32_t sk_base = smem_u32(&skh[0][0]);

        #pragma unroll
        for (int ks = 0; ks < 4; ks++) {
            uint32_t bfrag[2];
            {
                int l = lane & 15;
                int row = warp * 8 + (l & 7);
                int col = ks * 16 + ((l >> 3) & 1) * 8;
                ldmatrix_x2(bfrag, sk_base + (row * QK_STRIDE + col) * 2);
            }
            #pragma unroll
            for (int mt = 0; mt < 2; mt++) {
                uint32_t afrag[4];
                int row = mt * 16 + (lane & 15);
                int col = ks * 16 + (lane >> 4) * 8;
                ldmatrix_x4(afrag, sq_base + (row * QK_STRIDE + col) * 2);
                mma16(c[mt], afrag, bfrag);
            }
        }

        // exp + mask + store valid elements.
        // c[mt][{0,1}] -> row mt*16 + lane/4,     cols 8w+2(lane%4)+{0,1}
        // c[mt][{2,3}] -> row mt*16 + lane/4 + 8, same cols
        int jc = warp * 8 + 2 * (lane & 3);
        bool jv0 = (jc < SEQ), jv1 = (jc + 1 < SEQ);
        float m0 = (jc < len) ? 1.f : 0.f;
        float m1 = (jc + 1 < len) ? 1.f : 0.f;
        #pragma unroll
        for (int mt = 0; mt < 2; mt++) {
            #pragma unroll
            for (int hrow = 0; hrow < 2; hrow++) {
                int r = mt * 16 + (lane >> 2) + hrow * 8;
                if (r < SEQ) {
                    if (jv0) ssc[r][jc]     = m0 * __expf(c[mt][2 * hrow]     * 0.125f);
                    if (jv1) ssc[r][jc + 1] = m1 * __expf(c[mt][2 * hrow + 1] * 0.125f);
                }
            }
        }
    }
    __syncthreads();

    if (tid < SEQ) {
        float s = 0.f;
        #pragma unroll
        for (int j = 0; j < SEQ; j++) s += ssc[tid][j];
        sinv[tid] = 1.f / (s + 1e-8f);
    }
    __syncthreads();

    for (int e = tid; e < SEQ * SEQ; e += 128) {
        int i = e % SEQ, j = e / SEQ;
        wgtT[j][i] = ssc[i][j] * sinv[i] - (float)((i > j) ? (i - j) : (j - i));
    }
    __syncthreads();

    // Output: 4 rows x 4 cols per thread on threads 0..79
    if (tid < 80) {
        int i0 = (tid / 16) * 4;
        int d0 = (tid & 15) * 4;
        float4 o0 = {0, 0, 0, 0}, o1 = {0, 0, 0, 0}, o2 = {0, 0, 0, 0}, o3 = {0, 0, 0, 0};
        #pragma unroll
        for (int j = 0; j < SEQ; j++) {
            float4 vv = *(const float4*)&sv[j][d0];
            float4 w  = *(const float4*)&wgtT[j][i0];
            o0.x += w.x * vv.x; o0.y += w.x * vv.y; o0.z += w.x * vv.z; o0.w += w.x * vv.w;
            o1.x += w.y * vv.x; o1.y += w.y * vv.y; o1.z += w.y * vv.z; o1.w += w.y * vv.w;
            o2.x += w.z * vv.x; o2.y += w.z * vv.y; o2.z += w.z * vv.z; o2.w += w.z * vv.w;
            o3.x += w.w * vv.x; o3.y += w.w * vv.y; o3.z += w.w * vv.z; o3.w += w.w * vv.w;
        }
        size_t base = (size_t)(b * SEQ + i0) * D_MODEL + h * DK + d0;
        *(float4*)&out[base]               = o0;
        *(float4*)&out[base + D_MODEL]     = o1;
        *(float4*)&out[base + 2 * D_MODEL] = o2;
        *(float4*)&out[base + 3 * D_MODEL] = o3;
    }
}

// ---------------------------------------------------------------------------
// Inputs (metadata order): Q, W_Q, b_Q, W_K, b_K, W_V, b_V, length
// ---------------------------------------------------------------------------
extern "C" void kernel_launch(void* const* d_in, const int* in_sizes, int n_in,
                              void* d_out, int out_size)
{
    const float* X  = (const float*)d_in[0];
    const float* Wq = (const float*)d_in[1];
    const float* bq = (const float*)d_in[2];
    const float* Wk = (const float*)d_in[3];
    const float* bk = (const float*)d_in[4];
    const float* Wv = (const float*)d_in[5];
    const float* bv = (const float*)d_in[6];
    const int*   ln = (const int*)d_in[7];

    f2h_multi<<<XBLKS + 3 * WBLKS, 256>>>(X, Wq, Wk, Wv);

    cudaFuncSetAttribute(proj_gemm,
                         cudaFuncAttributeMaxDynamicSharedMemorySize, GM_SMEM_BYTES);

    dim3 grid(3 * (D_MODEL / GM_BN), M_TOTAL / GM_BM);   // (24, 320)
    proj_gemm<<<grid, 256, GM_SMEM_BYTES>>>(bq, bk, bv);

    attn_kernel<<<BATCH * NHEADS, 128>>>(ln, (float*)d_out);
}